// round 17
// baseline (speedup 1.0000x reference)
#include <cuda_runtime.h>
#include <cuda_fp16.h>
#include <math.h>

// ---------------- problem constants ----------------
#define Bv   2
#define Cch  256
#define Nn   32768           // D*H*W
#define Ss   256
#define TDd  512
#define NH   8
#define HD   32
#define QSCALE 0.2550396392825023f    // 32^-0.5 * log2(e)

// ---------------- scratch ----------------
__device__ __half g_krotH[Bv * NH * Ss * HD];          // [b,h,s,hd]
__device__ __half g_vT   [Bv * NH * HD * Ss];          // [b,h,hd,s]
__device__ __half g_qrotH[(size_t)Bv * NH * Nn * HD];  // [b,h,n,hd]  pre-scaled
__device__ __half g_attH [(size_t)Bv * Nn * Cch];      // [b,n,c]
__device__ __half g_owT  [Cch * Cch];                  // o_w transposed [c][k] fp16
__device__ __half g_qwT  [Cch * Cch];                  // q_w transposed [c][k] fp16

// ---------------- helpers ----------------
__device__ __forceinline__ void mma16(float c[4], const unsigned a[4],
                                      unsigned b0, unsigned b1) {
    asm volatile(
        "mma.sync.aligned.m16n8k16.row.col.f32.f16.f16.f32 "
        "{%0,%1,%2,%3},{%4,%5,%6,%7},{%8,%9},{%0,%1,%2,%3};"
        : "+f"(c[0]), "+f"(c[1]), "+f"(c[2]), "+f"(c[3])
        : "r"(a[0]), "r"(a[1]), "r"(a[2]), "r"(a[3]), "r"(b0), "r"(b1));
}

__device__ __forceinline__ void cpasync16(unsigned dst, const void* src) {
    asm volatile("cp.async.ca.shared.global [%0], [%1], 16;" :: "r"(dst), "l"(src));
}
#define CP_COMMIT()  asm volatile("cp.async.commit_group;")
#define CP_WAIT(n)   asm volatile("cp.async.wait_group %0;" :: "n"(n))

// ---------------------------------------------------------------------------
// Kernel 0: transpose W [k][c] fp32 -> {g_owT|g_qwT} [c][k] fp16.
// ---------------------------------------------------------------------------
__global__ void wt_kernel(const float* __restrict__ src, int dst_sel)
{
    __half* __restrict__ dst = dst_sel ? g_qwT : g_owT;
    __shared__ float t[32][33];
    const int tx = threadIdx.x & 31;
    const int ty = threadIdx.x >> 5;
    const int c0 = (blockIdx.x & 7) * 32;
    const int k0 = (blockIdx.x >> 3) * 32;
    #pragma unroll
    for (int r = ty; r < 32; r += 8)
        t[r][tx] = src[(size_t)(k0 + r) * Cch + c0 + tx];
    __syncthreads();
    #pragma unroll
    for (int r = ty; r < 32; r += 8)
        dst[(size_t)(c0 + r) * Cch + k0 + tx] = __float2half(t[tx][r]);
}

// ---------------------------------------------------------------------------
// Kernel 1: text side (K/V proj, MLP phase, rope on K). 64 CTAs, tiny. FFMA.
// ---------------------------------------------------------------------------
__global__ void text_kernel(const float* __restrict__ text,
                            const float* __restrict__ k_w, const float* __restrict__ k_b,
                            const float* __restrict__ v_w, const float* __restrict__ v_b,
                            const float* __restrict__ m1_w, const float* __restrict__ m1_b,
                            const float* __restrict__ m2_w, const float* __restrict__ m2_b)
{
    __shared__ float t_s[8][TDd];
    __shared__ float h_s[8][Cch];
    __shared__ float k_s[8][Cch];

    const int tid  = threadIdx.x;
    const int row0 = blockIdx.x * 8;

    #pragma unroll
    for (int r = 0; r < 8; r++) {
        t_s[r][tid]       = text[(size_t)(row0 + r) * TDd + tid];
        t_s[r][tid + 256] = text[(size_t)(row0 + r) * TDd + tid + 256];
    }
    __syncthreads();

    float ka[8], va[8], ha[8];
    #pragma unroll
    for (int r = 0; r < 8; r++) { ka[r] = k_b[tid]; va[r] = v_b[tid]; ha[r] = m1_b[tid]; }

    for (int i = 0; i < TDd; i++) {
        const float wk = k_w[i * Cch + tid];
        const float wv = v_w[i * Cch + tid];
        const float wm = m1_w[i * Cch + tid];
        #pragma unroll
        for (int r = 0; r < 8; r++) {
            const float t = t_s[r][i];
            ka[r] += t * wk;  va[r] += t * wv;  ha[r] += t * wm;
        }
    }

    #pragma unroll
    for (int r = 0; r < 8; r++) {
        const float x = ha[r];
        h_s[r][tid] = 0.5f * x * (1.0f + erff(x * 0.7071067811865475f));
        k_s[r][tid] = ka[r];
    }
    __syncthreads();

    float pa[8];
    #pragma unroll
    for (int r = 0; r < 8; r++) pa[r] = m2_b[tid];
    for (int i = 0; i < Cch; i++) {
        const float wm2 = m2_w[i * Cch + tid];
        #pragma unroll
        for (int r = 0; r < 8; r++) pa[r] += h_s[r][i] * wm2;
    }

    const int j    = tid & 31;
    const int head = tid >> 5;
    const int part = (j < 16) ? tid + 16 : tid - 16;
    const float sgn = (j < 16) ? -1.0f : 1.0f;

    #pragma unroll
    for (int r = 0; r < 8; r++) {
        const int row = row0 + r;
        const int b = row >> 8;
        const int s = row & 255;
        float sf, cf;
        sincosf(pa[r], &sf, &cf);
        const float krot = k_s[r][tid] * cf + sgn * k_s[r][part] * sf;
        const int bh = b * NH + head;
        g_krotH[(bh * Ss + s) * HD + j]  = __float2half(krot);
        g_vT  [(bh * HD + j) * Ss + s]   = __float2half(va[r]);
    }
}

// ---------------------------------------------------------------------------
// Kernel 2: Q projection, FP16 m16n8k16, CTA = 32 tokens x 256 cols (8 warps,
// warp tile 16x64, 32 accums/thread) -> 3 CTAs/SM.
// smem halves: A0[32][40] A1 | W0[256][40] W1 = 23040 halves (46KB);
// OUT fp32 [32][258] overlays staging; TB rope tables persist after staging.
// ---------------------------------------------------------------------------
#define QH_A0  0
#define QH_A1  1280           // 32*40
#define QH_W0  2560
#define QH_W1  12800          // +256*40
#define QH_END 23040          // halves
#define QTBf   11520          // float offset of rope tables (= QH_END/2)
#define QJ_FLOATS (QTBf + 2048)
#define QJ_BYTES (QJ_FLOATS * 4)   // 54.3KB -> 3 CTAs/SM

__global__ void __launch_bounds__(256, 3) qproj_kernel(const float* __restrict__ fv,
                                                       const float* __restrict__ qb)
{
    extern __shared__ float sm[];
    __half* smh = (__half*)sm;
    const unsigned smu = (unsigned)__cvta_generic_to_shared(sm);
    float* TB = sm + QTBf;

    const int tid  = threadIdx.x;
    const int w    = tid >> 5;
    const int lane = tid & 31;
    const int g    = lane >> 2;
    const int tg   = lane & 3;
    const int b    = blockIdx.x >> 10;
    const int n0   = (blockIdx.x & 1023) << 5;
    const int m0   = (w >> 2) * 16;       // 0 or 16
    const int cg   = w & 3;

    // ---- build rope tables (4 sincos per thread) ----
    #pragma unroll
    for (int e = 0; e < 4; e++) {
        const int idx = tid + e * 256;
        const int pos = idx >> 5;
        const int jj  = idx & 31;
        float ex;
        if (jj < 10)      { const int z = jj;      ex = ((z < 5) ? z : z - 5) / 5.0f; }
        else if (jj < 20) { const int y = jj - 10; ex = ((y < 5) ? y : y - 5) / 5.0f; }
        else              { const int x = jj - 20; ex = ((x < 6) ? x : x - 6) / 6.0f; }
        const float invf = expf(-ex * 9.210340371976184f);
        float sf, cf;
        __sincosf((float)pos * invf, &sf, &cf);
        TB[idx]        = cf;
        TB[1024 + idx] = sf;
    }

    const float* __restrict__ fvb = fv + (size_t)b * Cch * Nn;

    float acc[8][4];
    #pragma unroll
    for (int nt = 0; nt < 8; nt++)
        #pragma unroll
        for (int i = 0; i < 4; i++) acc[nt][i] = 0.0f;

    // ---- prefetch iter 0: A synchronously (transpose), W via cp.async ----
    {
        #pragma unroll
        for (int r = 0; r < 4; r++) {
            const int idx = tid + r * 256;
            const int kk = idx >> 5, nn = idx & 31;
            smh[QH_A0 + nn * 40 + kk] = __float2half(fvb[(size_t)kk * Nn + n0 + nn]);
        }
        #pragma unroll
        for (int r = 0; r < 4; r++) {
            const int idx = tid + r * 256;
            const int row = idx >> 2, cc = idx & 3;
            cpasync16(smu + (QH_W0 + row * 40) * 2 + cc * 16,
                      g_qwT + (size_t)row * Cch + cc * 8);
        }
        CP_COMMIT();
    }

    for (int it = 0; it < 8; it++) {
        const int abuf = (it & 1) ? QH_A1 : QH_A0;
        const int wbuf = (it & 1) ? QH_W1 : QH_W0;
        const int a2   = (it & 1) ? QH_A0 : QH_A1;
        float aval[4];
        if (it < 7) {
            const int k1 = (it + 1) * 32;
            #pragma unroll
            for (int r = 0; r < 4; r++) {
                const int idx = tid + r * 256;
                const int kk = idx >> 5, nn = idx & 31;
                aval[r] = fvb[(size_t)(k1 + kk) * Nn + n0 + nn];
            }
            const int w2 = (it & 1) ? QH_W0 : QH_W1;
            #pragma unroll
            for (int r = 0; r < 4; r++) {
                const int idx = tid + r * 256;
                const int row = idx >> 2, cc = idx & 3;
                cpasync16(smu + (w2 + row * 40) * 2 + cc * 16,
                          g_qwT + (size_t)row * Cch + k1 + cc * 8);
            }
            CP_COMMIT();
            CP_WAIT(1);
        } else {
            CP_WAIT(0);
        }
        __syncthreads();

        unsigned a[2][4];
        #pragma unroll
        for (int ks = 0; ks < 2; ks++) {
            const int kb = ks * 16 + 2 * tg;
            const int row = m0 + g;
            a[ks][0] = *(const unsigned*)&smh[abuf + row * 40 + kb];
            a[ks][1] = *(const unsigned*)&smh[abuf + (row + 8) * 40 + kb];
            a[ks][2] = *(const unsigned*)&smh[abuf + row * 40 + kb + 8];
            a[ks][3] = *(const unsigned*)&smh[abuf + (row + 8) * 40 + kb + 8];
        }
        #pragma unroll
        for (int nt = 0; nt < 8; nt++) {
            const int cA = cg * 64 + nt * 8 + g;
            #pragma unroll
            for (int ks = 0; ks < 2; ks++) {
                const int kb = ks * 16 + 2 * tg;
                const unsigned b0 = *(const unsigned*)&smh[wbuf + cA * 40 + kb];
                const unsigned b1 = *(const unsigned*)&smh[wbuf + cA * 40 + kb + 8];
                mma16(acc[nt], a[ks], b0, b1);
            }
        }

        if (it < 7) {
            #pragma unroll
            for (int r = 0; r < 4; r++) {
                const int idx = tid + r * 256;
                const int kk = idx >> 5, nn = idx & 31;
                smh[a2 + nn * 40 + kk] = __float2half(aval[r]);
            }
        }
        __syncthreads();
    }

    // write accums into OUT fp32 [32][258] (overlays staging)
    {
        const int row = m0 + g;
        #pragma unroll
        for (int nt = 0; nt < 8; nt++) {
            const int col = cg * 64 + nt * 8 + 2 * tg;
            *(float2*)&sm[row * 258 + col]       = make_float2(acc[nt][0], acc[nt][1]);
            *(float2*)&sm[(row + 8) * 258 + col] = make_float2(acc[nt][2], acc[nt][3]);
        }
    }
    __syncthreads();

    // epilogue: bias + 3D rope + QSCALE, write fp16; thread = channel c
    const int c    = tid;
    const int j    = c & 31;
    const int head = c >> 5;
    const int sel  = (j < 10) ? 0 : (j < 20) ? 1 : 2;
    const int part  = (j < 16) ? c + 16 : c - 16;
    const float sgn = (j < 16) ? -1.0f : 1.0f;
    const float qbc = qb[c], qbp = qb[part];

    __half* __restrict__ qo = g_qrotH + (((size_t)(b * NH + head)) * Nn) * HD + j;
    for (int nn = 0; nn < 32; nn++) {
        const int n  = n0 + nn;
        const int dz = n >> 10;
        const int hy = (n >> 5) & 31;
        const int wx = n & 31;
        const int posv = (sel == 0) ? dz : (sel == 1) ? hy : wx;
        const float cf = TB[posv * 32 + j];
        const float sf = TB[1024 + posv * 32 + j];
        const float qv = sm[nn * 258 + c]    + qbc;
        const float pv = sm[nn * 258 + part] + qbp;
        qo[(size_t)n * HD] = __float2half((qv * cf + sgn * pv * sf) * QSCALE);
    }
}

// ---------------------------------------------------------------------------
// Kernel 3: flash attention, FP16 m16n8k16 (byte-identical to round 16).
// ---------------------------------------------------------------------------
#define AQS  0
#define AKF  9216
#define AVT  (AKF + 256*40)          // 19456
#define AT_HALVES (AVT + 32*264)     // 27904
#define AT_BYTES (AT_HALVES * 2)     // 55808

__global__ void __launch_bounds__(256, 3) attn_kernel()
{
    extern __shared__ __half smh[];
    const unsigned smu = (unsigned)__cvta_generic_to_shared(smh);

    const int tid  = threadIdx.x;
    const int w    = tid >> 5;
    const int lane = tid & 31;
    const int g    = lane >> 2;
    const int tg   = lane & 3;
    const int n0   = blockIdx.x * 128;
    const int h    = blockIdx.y;
    const int b    = blockIdx.z;
    const size_t bh = (size_t)(b * NH + h);
    const int qr   = w * 16 + g;

    {
        #pragma unroll
        for (int r = 0; r < 2; r++) {
            const int idx = tid + r * 256;
            const int row = idx >> 2, cc = idx & 3;
            cpasync16(smu + (AQS + row * 40) * 2 + cc * 16,
                      g_qrotH + (bh * Nn + n0 + row) * HD + cc * 8);
        }
        #pragma unroll
        for (int r = 0; r < 4; r++) {
            const int idx = tid + r * 256;
            const int row = idx >> 2, cc = idx & 3;
            cpasync16(smu + (AKF + row * 40) * 2 + cc * 16,
                      g_krotH + (bh * Ss + row) * HD + cc * 8);
        }
        #pragma unroll
        for (int r = 0; r < 4; r++) {
            const int idx = tid + r * 256;
            const int row = idx >> 5, cc = idx & 31;
            cpasync16(smu + (AVT + row * 264) * 2 + cc * 16,
                      g_vT + (bh * HD + row) * Ss + cc * 8);
        }
        CP_COMMIT();
        CP_WAIT(0);
    }
    __syncthreads();

    unsigned aq[2][4];
    #pragma unroll
    for (int ks = 0; ks < 2; ks++) {
        const int kb = ks * 16 + 2 * tg;
        aq[ks][0] = *(const unsigned*)&smh[AQS + qr * 40 + kb];
        aq[ks][1] = *(const unsigned*)&smh[AQS + (qr + 8) * 40 + kb];
        aq[ks][2] = *(const unsigned*)&smh[AQS + qr * 40 + kb + 8];
        aq[ks][3] = *(const unsigned*)&smh[AQS + (qr + 8) * 40 + kb + 8];
    }
    __syncthreads();

    float m0, m1, l0, l1;
    float o[4][4];
    #pragma unroll
    for (int nt = 0; nt < 4; nt++)
        #pragma unroll
        for (int i = 0; i < 4; i++) o[nt][i] = 0.0f;

    #pragma unroll
    for (int ch = 0; ch < 4; ch++) {
        float c[8][4];
        #pragma unroll
        for (int nt = 0; nt < 8; nt++)
            #pragma unroll
            for (int i = 0; i < 4; i++) c[nt][i] = 0.0f;

        #pragma unroll
        for (int nt = 0; nt < 8; nt++) {
            const int key = ch * 64 + nt * 8 + g;
            #pragma unroll
            for (int ks = 0; ks < 2; ks++) {
                const int kb = ks * 16 + 2 * tg;
                const unsigned b0 = *(const unsigned*)&smh[AKF + key * 40 + kb];
                const unsigned b1 = *(const unsigned*)&smh[AKF + key * 40 + kb + 8];
                mma16(c[nt], aq[ks], b0, b1);
            }
        }

        float cm0 = -1e30f, cm1 = -1e30f;
        #pragma unroll
        for (int nt = 0; nt < 8; nt++) {
            cm0 = fmaxf(cm0, fmaxf(c[nt][0], c[nt][1]));
            cm1 = fmaxf(cm1, fmaxf(c[nt][2], c[nt][3]));
        }
        cm0 = fmaxf(cm0, __shfl_xor_sync(0xffffffffu, cm0, 1));
        cm0 = fmaxf(cm0, __shfl_xor_sync(0xffffffffu, cm0, 2));
        cm1 = fmaxf(cm1, __shfl_xor_sync(0xffffffffu, cm1, 1));
        cm1 = fmaxf(cm1, __shfl_xor_sync(0xffffffffu, cm1, 2));

        float sc0 = 1.0f, sc1 = 1.0f;
        if (ch == 0) {
            m0 = cm0; m1 = cm1;
        } else {
            const float mn0 = fmaxf(m0, cm0);
            const float mn1 = fmaxf(m1, cm1);
            sc0 = exp2f(m0 - mn0);
            sc1 = exp2f(m1 - mn1);
            m0 = mn0; m1 = mn1;
        }

        float s0 = 0.0f, s1 = 0.0f;
        #pragma unroll
        for (int nt = 0; nt < 8; nt++) {
            const float p0 = exp2f(c[nt][0] - m0);
            const float p1 = exp2f(c[nt][1] - m0);
            const float p2 = exp2f(c[nt][2] - m1);
            const float p3 = exp2f(c[nt][3] - m1);
            s0 += p0 + p1;  s1 += p2 + p3;
            *(__half2*)&smh[AQS + qr * 72 + nt * 8 + 2 * tg]       = __floats2half2_rn(p0, p1);
            *(__half2*)&smh[AQS + (qr + 8) * 72 + nt * 8 + 2 * tg] = __floats2half2_rn(p2, p3);
        }
        s0 += __shfl_xor_sync(0xffffffffu, s0, 1);
        s0 += __shfl_xor_sync(0xffffffffu, s0, 2);
        s1 += __shfl_xor_sync(0xffffffffu, s1, 1);
        s1 += __shfl_xor_sync(0xffffffffu, s1, 2);
        if (ch == 0) {
            l0 = s0;  l1 = s1;
        } else {
            l0 = l0 * sc0 + s0;
            l1 = l1 * sc1 + s1;
            #pragma unroll
            for (int nt = 0; nt < 4; nt++) {
                o[nt][0] *= sc0;  o[nt][1] *= sc0;
                o[nt][2] *= sc1;  o[nt][3] *= sc1;
            }
        }
        __syncwarp();

        #pragma unroll
        for (int ss = 0; ss < 4; ss++) {
            const int sb = ss * 16 + 2 * tg;
            unsigned a[4];
            a[0] = *(const unsigned*)&smh[AQS + qr * 72 + sb];
            a[1] = *(const unsigned*)&smh[AQS + (qr + 8) * 72 + sb];
            a[2] = *(const unsigned*)&smh[AQS + qr * 72 + sb + 8];
            a[3] = *(const unsigned*)&smh[AQS + (qr + 8) * 72 + sb + 8];
            const int s0i = ch * 64 + ss * 16 + 2 * tg;
            #pragma unroll
            for (int nt = 0; nt < 4; nt++) {
                const int hd = nt * 8 + g;
                const unsigned b0 = *(const unsigned*)&smh[AVT + hd * 264 + s0i];
                const unsigned b1 = *(const unsigned*)&smh[AVT + hd * 264 + s0i + 8];
                mma16(o[nt], a, b0, b1);
            }
        }
        __syncwarp();
    }

    const float r0 = 1.0f / l0;
    const float r1 = 1.0f / l1;
    #pragma unroll
    for (int nt = 0; nt < 4; nt++) {
        const int hd = nt * 8 + 2 * tg;
        __half* p0 = g_attH + ((size_t)(b * Nn + n0 + qr)) * Cch + h * HD + hd;
        __half* p1 = g_attH + ((size_t)(b * Nn + n0 + qr + 8)) * Cch + h * HD + hd;
        *(__half2*)p0 = __floats2half2_rn(o[nt][0] * r0, o[nt][1] * r0);
        *(__half2*)p1 = __floats2half2_rn(o[nt][2] * r1, o[nt][3] * r1);
    }
}

// ---------------------------------------------------------------------------
// Kernel 4: O projection + transpose, FP16 m16n8k16, CTA = 32 tokens x 256
// cols (warp tile 16x64, 32 accums) -> 3 CTAs/SM. cp.async double-buffered.
// smem halves: A0[32][40] A1 | W0[256][40] W1; OUT fp32 [32][258] overlays.
// ---------------------------------------------------------------------------
#define OH_A0  0
#define OH_A1  1280
#define OH_W0  2560
#define OH_W1  12800
#define OJ_BYTES (11520 * 4)   // max(staging 23040 halves, OUT 8256 fl) = 46KB

__global__ void __launch_bounds__(256, 3) oproj_kernel(const float* __restrict__ ob,
                                                       float* __restrict__ out)
{
    extern __shared__ float sm[];
    __half* smh = (__half*)sm;
    const unsigned smu = (unsigned)__cvta_generic_to_shared(sm);

    const int tid  = threadIdx.x;
    const int w    = tid >> 5;
    const int lane = tid & 31;
    const int g    = lane >> 2;
    const int tg   = lane & 3;
    const int b    = blockIdx.x >> 10;
    const int n0   = (blockIdx.x & 1023) << 5;
    const int m0   = (w >> 2) * 16;
    const int cg   = w & 3;

    const __half* __restrict__ att = g_attH + ((size_t)(b * Nn + n0)) * Cch;

    float acc[8][4];
    #pragma unroll
    for (int nt = 0; nt < 8; nt++)
        #pragma unroll
        for (int i = 0; i < 4; i++) acc[nt][i] = 0.0f;

    {
        if (tid < 128) {     // A: 32 rows x 64B = 128 chunks
            const int row = tid >> 2, cc = tid & 3;
            cpasync16(smu + (OH_A0 + row * 40) * 2 + cc * 16,
                      att + (size_t)row * Cch + cc * 8);
        }
        #pragma unroll
        for (int r = 0; r < 4; r++) {
            const int idx = tid + r * 256;
            const int row = idx >> 2, cc = idx & 3;
            cpasync16(smu + (OH_W0 + row * 40) * 2 + cc * 16,
                      g_owT + (size_t)row * Cch + cc * 8);
        }
        CP_COMMIT();
    }

    for (int it = 0; it < 8; it++) {
        const int abuf = (it & 1) ? OH_A1 : OH_A0;
        const int wbuf = (it & 1) ? OH_W1 : OH_W0;
        if (it < 7) {
            const int k1 = (it + 1) * 32;
            const int a2 = (it & 1) ? OH_A0 : OH_A1;
            const int w2 = (it & 1) ? OH_W0 : OH_W1;
            if (tid < 128) {
                const int row = tid >> 2, cc = tid & 3;
                cpasync16(smu + (a2 + row * 40) * 2 + cc * 16,
                          att + (size_t)row * Cch + k1 + cc * 8);
            }
            #pragma unroll
            for (int r = 0; r < 4; r++) {
                const int idx = tid + r * 256;
                const int row = idx >> 2, cc = idx & 3;
                cpasync16(smu + (w2 + row * 40) * 2 + cc * 16,
                          g_owT + (size_t)row * Cch + k1 + cc * 8);
            }
            CP_COMMIT();
            CP_WAIT(1);
        } else {
            CP_WAIT(0);
        }
        __syncthreads();

        unsigned a[2][4];
        #pragma unroll
        for (int ks = 0; ks < 2; ks++) {
            const int kb = ks * 16 + 2 * tg;
            const int row = m0 + g;
            a[ks][0] = *(const unsigned*)&smh[abuf + row * 40 + kb];
            a[ks][1] = *(const unsigned*)&smh[abuf + (row + 8) * 40 + kb];
            a[ks][2] = *(const unsigned*)&smh[abuf + row * 40 + kb + 8];
            a[ks][3] = *(const unsigned*)&smh[abuf + (row + 8) * 40 + kb + 8];
        }
        #pragma unroll
        for (int nt = 0; nt < 8; nt++) {
            const int cA = cg * 64 + nt * 8 + g;
            #pragma unroll
            for (int ks = 0; ks < 2; ks++) {
                const int kb = ks * 16 + 2 * tg;
                const unsigned b0 = *(const unsigned*)&smh[wbuf + cA * 40 + kb];
                const unsigned b1 = *(const unsigned*)&smh[wbuf + cA * 40 + kb + 8];
                mma16(acc[nt], a[ks], b0, b1);
            }
        }
        __syncthreads();
    }

    {
        const int row = m0 + g;
        #pragma unroll
        for (int nt = 0; nt < 8; nt++) {
            const int col = cg * 64 + nt * 8 + 2 * tg;
            *(float2*)&sm[row * 258 + col]       = make_float2(acc[nt][0], acc[nt][1]);
            *(float2*)&sm[(row + 8) * 258 + col] = make_float2(acc[nt][2], acc[nt][3]);
        }
    }
    __syncthreads();

    // transposed coalesced store: out[b][c][n0 + token], token = lane (0..31)
    float* __restrict__ obp = out + (size_t)b * Cch * Nn + n0 + lane;
    #pragma unroll 4
    for (int it = 0; it < 32; it++) {
        const int c = it * 8 + w;
        obp[(size_t)c * Nn] = sm[lane * 258 + c] + ob[c];
    }
}

// ---------------------------------------------------------------------------
extern "C" void kernel_launch(void* const* d_in, const int* in_sizes, int n_in,
                              void* d_out, int out_size)
{
    const float* fused_visual = (const float*)d_in[0];
    const float* text_emb     = (const float*)d_in[1];
    const float* q_w = (const float*)d_in[2];
    const float* q_b = (const float*)d_in[3];
    const float* k_w = (const float*)d_in[4];
    const float* k_b = (const float*)d_in[5];
    const float* v_w = (const float*)d_in[6];
    const float* v_b = (const float*)d_in[7];
    const float* o_w = (const float*)d_in[8];
    const float* o_b = (const float*)d_in[9];
    const float* m1_w = (const float*)d_in[10];
    const float* m1_b = (const float*)d_in[11];
    const float* m2_w = (const float*)d_in[12];
    const float* m2_b = (const float*)d_in[13];
    float* out = (float*)d_out;

    static int smem_ok = -1;
    if (smem_ok < 0) {
        cudaFuncSetAttribute(attn_kernel,  cudaFuncAttributeMaxDynamicSharedMemorySize, AT_BYTES);
        cudaFuncSetAttribute(qproj_kernel, cudaFuncAttributeMaxDynamicSharedMemorySize, QJ_BYTES);
        cudaFuncSetAttribute(oproj_kernel, cudaFuncAttributeMaxDynamicSharedMemorySize, OJ_BYTES);
        smem_ok = 1;
    }

    text_kernel<<<(Bv * Ss) / 8, 256>>>(text_emb, k_w, k_b, v_w, v_b, m1_w, m1_b, m2_w, m2_b);
    wt_kernel<<<64, 256>>>(o_w, 0);
    wt_kernel<<<64, 256>>>(q_w, 1);
    qproj_kernel<<<Bv * (Nn / 32), 256, QJ_BYTES>>>(fused_visual, q_b);
    attn_kernel<<<dim3(Nn / 128, NH, Bv), 256, AT_BYTES>>>();
    oproj_kernel<<<Bv * (Nn / 32), 256, OJ_BYTES>>>(o_b, out);
}